// round 2
// baseline (speedup 1.0000x reference)
#include <cuda_runtime.h>
#include <cstdint>

#define BATCH 8192
#define DIN   1024
#define DSAE  16384
#define TOPK  32
#define NC_MAX 64          // max boundary candidates per row for fp64 refinement
#define BAND_EPS 1e-3f     // ambiguity band around threshold (noise is ~1e-6)

// ---------------- scratch (no allocations allowed) ----------------
__device__ int    g_tk_idx[BATCH * TOPK];
__device__ float  g_tk_val[BATCH * TOPK];
__device__ double g_loss_sum;
__device__ float  g_l0_sum;

__global__ void init_kernel() {
    g_loss_sum = 0.0;
    g_l0_sum   = 0.0f;
}

// ---------------- encoder GEMM: C = relu(A @ B + bias) ----------------
// A: [8192,1024] row-major (x), B: [1024,16384] row-major (W_enc)
// Tile 128x128x16, 256 threads, 8x8 per thread, double-buffered smem.
__global__ __launch_bounds__(256, 2)
void gemm_relu_kernel(const float* __restrict__ A, const float* __restrict__ B,
                      const float* __restrict__ bias, float* __restrict__ C)
{
    __shared__ float As[2][16][128];
    __shared__ float Bs[2][16][128];

    const int tid = threadIdx.x;
    const int m0 = blockIdx.y * 128;
    const int n0 = blockIdx.x * 128;
    const int tx = tid & 15, ty = tid >> 4;
    const int tm = ty * 8,   tn = tx * 8;

    const int a_row = tid >> 2;          // 0..63 (+64 for second)
    const int a_k   = (tid & 3) << 2;    // 0,4,8,12
    const int b_r   = tid >> 5;          // 0..7 (+8 for second)
    const int b_c   = (tid & 31) << 2;   // 0..124

    float acc[8][8] = {};

#define LOAD_TILE(kt, buf) do {                                                     \
    const int k0 = (kt) << 4;                                                       \
    _Pragma("unroll")                                                               \
    for (int h = 0; h < 2; h++) {                                                   \
        const int row = a_row + h * 64;                                             \
        float4 v = *reinterpret_cast<const float4*>(                                \
            &A[(size_t)(m0 + row) * DIN + k0 + a_k]);                               \
        As[buf][a_k + 0][row] = v.x;                                                \
        As[buf][a_k + 1][row] = v.y;                                                \
        As[buf][a_k + 2][row] = v.z;                                                \
        As[buf][a_k + 3][row] = v.w;                                                \
    }                                                                               \
    _Pragma("unroll")                                                               \
    for (int h = 0; h < 2; h++) {                                                   \
        const int r = b_r + h * 8;                                                  \
        *reinterpret_cast<float4*>(&Bs[buf][r][b_c]) =                              \
            *reinterpret_cast<const float4*>(&B[(size_t)(k0 + r) * DSAE + n0 + b_c]); \
    }                                                                               \
} while (0)

    LOAD_TILE(0, 0);
    __syncthreads();

    const int nk = DIN / 16;  // 64
    for (int kt = 0; kt < nk; kt++) {
        const int buf = kt & 1;
        if (kt + 1 < nk) LOAD_TILE(kt + 1, buf ^ 1);
        #pragma unroll
        for (int k = 0; k < 16; k++) {
            float a[8], b[8];
            *(float4*)&a[0] = *(float4*)&As[buf][k][tm];
            *(float4*)&a[4] = *(float4*)&As[buf][k][tm + 4];
            *(float4*)&b[0] = *(float4*)&Bs[buf][k][tn];
            *(float4*)&b[4] = *(float4*)&Bs[buf][k][tn + 4];
            #pragma unroll
            for (int i = 0; i < 8; i++)
                #pragma unroll
                for (int j = 0; j < 8; j++)
                    acc[i][j] += a[i] * b[j];
        }
        __syncthreads();
    }
#undef LOAD_TILE

    #pragma unroll
    for (int i = 0; i < 8; i++) {
        const size_t row = (size_t)(m0 + tm + i);
        #pragma unroll
        for (int j = 0; j < 8; j += 4) {
            const int col = n0 + tn + j;
            float4 bv = *reinterpret_cast<const float4*>(&bias[col]);
            float4 o;
            o.x = fmaxf(acc[i][j + 0] + bv.x, 0.0f);
            o.y = fmaxf(acc[i][j + 1] + bv.y, 0.0f);
            o.z = fmaxf(acc[i][j + 2] + bv.z, 0.0f);
            o.w = fmaxf(acc[i][j + 3] + bv.w, 0.0f);
            *reinterpret_cast<float4*>(&C[row * DSAE + col]) = o;
        }
    }
}

// ---------------- per-row top-32 radix select + fp64 boundary refinement ----------------
// One CTA per row. Row cached in smem as uint bits (relu => nonneg => uint order
// == float order). 4x 8-bit radix passes find the 32nd-largest threshold.
// If any unselected value lies within BAND_EPS of the threshold, the ranking at the
// boundary is ambiguous at fp32 noise scale -> recompute those few candidates' dot
// products exactly in fp64 and re-rank (tie -> lowest index, matching jax.lax.top_k).
__global__ __launch_bounds__(256)
void topk_kernel(float* __restrict__ H,
                 const float* __restrict__ x, const float* __restrict__ Wenc)
{
    extern __shared__ uint32_t sh[];   // 16384 uints = 64KB
    __shared__ int hist[256];
    __shared__ unsigned s_prefix;
    __shared__ int s_need, s_cnteq;
    __shared__ int s_cnt, s_pos;
    __shared__ uint32_t tiemask[512];  // 16384 bits
    __shared__ int s_nc, s_nselband;
    __shared__ int cand_idx[NC_MAX];
    __shared__ double cand_ref[NC_MAX];
    __shared__ double dred[256];
    __shared__ unsigned long long s_chosen;

    const int row = blockIdx.x;
    const int tid = threadIdx.x;
    float* hrow = H + (size_t)row * DSAE;

    // load row
    for (int i = tid; i < DSAE / 4; i += 256)
        ((uint4*)sh)[i] = ((const uint4*)hrow)[i];
    if (tid == 0) {
        s_prefix = 0u; s_need = TOPK; s_cnt = 0; s_pos = 0;
        s_nc = 0; s_nselband = 0; s_chosen = 0ull;
    }
    __syncthreads();

    // radix passes, MSB byte first
    for (int shift = 24; shift >= 0; shift -= 8) {
        hist[tid] = 0;
        __syncthreads();
        const uint32_t himask = (shift == 24) ? 0u : (0xFFFFFFFFu << (shift + 8));
        const uint32_t pfx = s_prefix;
        for (int i = tid; i < DSAE; i += 256) {
            uint32_t u = sh[i];
            if ((u & himask) == pfx)
                atomicAdd(&hist[(u >> shift) & 255], 1);
        }
        __syncthreads();
        if (tid == 0) {
            int need = s_need, above = 0, b = 255;
            for (; b > 0; b--) {
                if (above + hist[b] >= need) break;
                above += hist[b];
            }
            s_prefix |= ((unsigned)b) << shift;
            s_need = need - above;
            s_cnteq = hist[b];
        }
        __syncthreads();
    }

    const uint32_t T = s_prefix;
    const int r = s_need;          // how many == T to take
    const bool ties = (s_cnteq != r);
    const float Tf = __uint_as_float(T);

    if (ties) {
        // exact-duplicate threshold (ultra-rare): lowest-index equals, serial & deterministic
        for (int i = tid; i < 512; i += 256) tiemask[i] = 0u;
        __syncthreads();
        if (tid == 0) {
            int taken = 0;
            for (int i = 0; i < DSAE && taken < r; i++)
                if (sh[i] == T) { tiemask[i >> 5] |= 1u << (i & 31); taken++; }
        }
        __syncthreads();
    }

    // ---- boundary-ambiguity detection (skip in the exact-tie path) ----
    bool refine = false;
    if (!ties) {
        for (int i = tid; i < DSAE; i += 256) {
            const uint32_t u = sh[i];
            const float v = __uint_as_float(u);
            const bool selbase = (u >= T);
            const bool band = selbase ? (v < Tf + BAND_EPS) : (v > Tf - BAND_EPS);
            if (band) {
                const int p = atomicAdd(&s_nc, 1);
                if (p < NC_MAX) cand_idx[p] = i;
                if (selbase) atomicAdd(&s_nselband, 1);
            }
        }
        __syncthreads();
        const int nc = s_nc, nsb = s_nselband;
        // refine only if contested (some unselected candidate in band) and no overflow
        refine = (nc <= NC_MAX) && (nc > nsb) && (nsb > 0);

        if (refine) {
            // exact fp64 dot for each candidate feature
            for (int c = 0; c < nc; c++) {
                const int f = cand_idx[c];
                double p = 0.0;
                const float* xr = x + (size_t)row * DIN;
                for (int k = tid; k < DIN; k += 256)
                    p += (double)xr[k] * (double)Wenc[(size_t)k * DSAE + f];
                dred[tid] = p;
                __syncthreads();
                for (int s = 128; s > 0; s >>= 1) {
                    if (tid < s) dred[tid] += dred[tid + s];
                    __syncthreads();
                }
                if (tid == 0) cand_ref[c] = dred[0];
                __syncthreads();
            }
            // pick top nsb among candidates by (refined value desc, index asc)
            if (tid == 0) {
                unsigned long long chosen = 0ull;
                for (int t = 0; t < nsb; t++) {
                    int best = -1;
                    for (int c = 0; c < nc; c++) {
                        if ((chosen >> c) & 1ull) continue;
                        if (best < 0 ||
                            cand_ref[c] > cand_ref[best] ||
                            (cand_ref[c] == cand_ref[best] && cand_idx[c] < cand_idx[best]))
                            best = c;
                    }
                    chosen |= 1ull << best;
                }
                s_chosen = chosen;
            }
            __syncthreads();
        }
    }
    const int nc_f = s_nc;
    const unsigned long long chosen_f = s_chosen;

    // ---- sparsify + compact ----
    for (int i = tid; i < DSAE; i += 256) {
        const uint32_t u = sh[i];
        const float v = __uint_as_float(u);
        bool sel;
        if (ties) {
            if (u > T)       sel = true;
            else if (u == T) sel = ((tiemask[i >> 5] >> (i & 31)) & 1u) != 0;
            else             sel = false;
        } else if (refine) {
            const bool selbase = (u >= T);
            const bool band = selbase ? (v < Tf + BAND_EPS) : (v > Tf - BAND_EPS);
            if (band) {
                sel = false;
                for (int c = 0; c < nc_f; c++)
                    if (cand_idx[c] == i) { sel = ((chosen_f >> c) & 1ull) != 0; break; }
            } else {
                sel = selbase;
            }
        } else {
            sel = (u >= T);
        }
        hrow[i] = sel ? v : 0.0f;
        if (sel) {
            const int slot = atomicAdd(&s_cnt, 1);
            g_tk_idx[row * TOPK + slot] = i;
            g_tk_val[row * TOPK + slot] = v;
            if (u != 0u) atomicAdd(&s_pos, 1);
        }
    }
    __syncthreads();
    if (tid == 0) atomicAdd(&g_l0_sum, (float)s_pos);
}

// ---------------- decoder: x_hat = h_sparse @ W_dec + b_dec, + loss ----------------
__global__ __launch_bounds__(256)
void decoder_kernel(const float* __restrict__ x, const float* __restrict__ Wdec,
                    const float* __restrict__ bdec, float* __restrict__ xhat)
{
    __shared__ int   sidx[TOPK];
    __shared__ float sval[TOPK];
    __shared__ float red[256];

    const int row = blockIdx.x;
    const int tid = threadIdx.x;
    if (tid < TOPK) {
        sidx[tid] = g_tk_idx[row * TOPK + tid];
        sval[tid] = g_tk_val[row * TOPK + tid];
    }
    __syncthreads();

    const int c = tid * 4;  // 256 threads x 4 = 1024 cols
    float4 acc = *reinterpret_cast<const float4*>(&bdec[c]);
    #pragma unroll 4
    for (int j = 0; j < TOPK; j++) {
        const float v = sval[j];
        const float4 w = *reinterpret_cast<const float4*>(
            &Wdec[(size_t)sidx[j] * DIN + c]);
        acc.x += v * w.x;
        acc.y += v * w.y;
        acc.z += v * w.z;
        acc.w += v * w.w;
    }
    const float4 xv = *reinterpret_cast<const float4*>(&x[(size_t)row * DIN + c]);
    *reinterpret_cast<float4*>(&xhat[(size_t)row * DIN + c]) = acc;

    const float dx = acc.x - xv.x, dy = acc.y - xv.y;
    const float dz = acc.z - xv.z, dw = acc.w - xv.w;
    red[tid] = dx * dx + dy * dy + dz * dz + dw * dw;
    __syncthreads();
    for (int s = 128; s > 0; s >>= 1) {
        if (tid < s) red[tid] += red[tid + s];
        __syncthreads();
    }
    if (tid == 0) atomicAdd(&g_loss_sum, (double)red[0]);
}

__global__ void finalize_kernel(float* __restrict__ out_loss, float* __restrict__ out_l0)
{
    out_loss[0] = (float)(g_loss_sum / ((double)BATCH * (double)DIN));
    out_l0[0]   = g_l0_sum / (float)BATCH;
}

// ---------------- launch ----------------
extern "C" void kernel_launch(void* const* d_in, const int* in_sizes, int n_in,
                              void* d_out, int out_size)
{
    const float* x     = (const float*)d_in[0];
    const float* W_enc = (const float*)d_in[1];
    const float* b_enc = (const float*)d_in[2];
    const float* W_dec = (const float*)d_in[3];
    const float* b_dec = (const float*)d_in[4];

    float* out   = (float*)d_out;
    float* xhat  = out;                                   // [8192*1024]
    float* H     = out + (size_t)BATCH * DIN;             // [8192*16384]
    float* oloss = out + (size_t)BATCH * DIN + (size_t)BATCH * DSAE;
    float* ol0   = oloss + 1;

    (void)in_sizes; (void)n_in; (void)out_size;

    cudaFuncSetAttribute(topk_kernel,
                         cudaFuncAttributeMaxDynamicSharedMemorySize, DSAE * 4);

    init_kernel<<<1, 1>>>();

    dim3 gg(DSAE / 128, BATCH / 128);  // (128, 64)
    gemm_relu_kernel<<<gg, 256>>>(x, W_enc, b_enc, H);

    topk_kernel<<<BATCH, 256, DSAE * 4>>>(H, x, W_enc);

    decoder_kernel<<<BATCH, 256>>>(x, W_dec, b_dec, xhat);

    finalize_kernel<<<1, 1>>>(oloss, ol0);
}

// round 4
// speedup vs baseline: 2.3894x; 2.3894x over previous
#include <cuda_runtime.h>
#include <cuda_bf16.h>
#include <cstdint>

#define BATCH 8192
#define DIN   1024
#define DSAE  16384
#define TOPK  32
#define NC_MAX 64
#define BAND_EPS 1e-3f

// ---------------- scratch (no allocations allowed) ----------------
__device__ int    g_tk_idx[BATCH * TOPK];
__device__ float  g_tk_val[BATCH * TOPK];
__device__ double g_loss_sum;
__device__ float  g_l0_sum;
__device__ __align__(1024) __nv_bfloat16 g_Xh[BATCH * DIN];
__device__ __align__(1024) __nv_bfloat16 g_Xl[BATCH * DIN];
__device__ __align__(1024) __nv_bfloat16 g_Wh[(size_t)DSAE * DIN];  // W_enc^T hi
__device__ __align__(1024) __nv_bfloat16 g_Wl[(size_t)DSAE * DIN];  // W_enc^T lo

__global__ void init_kernel() {
    g_loss_sum = 0.0;
    g_l0_sum   = 0.0f;
}

// ---------------- prep: bf16 hi/lo split of x ----------------
__global__ __launch_bounds__(256)
void splitx_kernel(const float* __restrict__ x)
{
    const size_t i = (size_t)blockIdx.x * blockDim.x + threadIdx.x;
    const float v = x[i];
    const __nv_bfloat16 h = __float2bfloat16_rn(v);
    const float r = v - __bfloat162float(h);
    g_Xh[i] = h;
    g_Xl[i] = __float2bfloat16_rn(r);
}

// ---------------- prep: transpose + bf16 hi/lo split of W_enc ----------------
// W_enc [DIN][DSAE] -> Wh/Wl [DSAE][DIN] (K-major rows)
__global__ __launch_bounds__(256)
void splitw_kernel(const float* __restrict__ W)
{
    __shared__ float t[32][33];
    const int n0 = blockIdx.x * 32, k0 = blockIdx.y * 32;
    const int tx = threadIdx.x, ty = threadIdx.y;  // 32 x 8
    #pragma unroll
    for (int i = 0; i < 32; i += 8)
        t[ty + i][tx] = W[(size_t)(k0 + ty + i) * DSAE + n0 + tx];
    __syncthreads();
    #pragma unroll
    for (int i = 0; i < 32; i += 8) {
        const float v = t[tx][ty + i];  // = W[k0+tx][n0+ty+i]
        const __nv_bfloat16 h = __float2bfloat16_rn(v);
        const float r = v - __bfloat162float(h);
        const size_t o = (size_t)(n0 + ty + i) * DIN + k0 + tx;
        g_Wh[o] = h;
        g_Wl[o] = __float2bfloat16_rn(r);
    }
}

// ---------------- helpers ----------------
__device__ __forceinline__ uint32_t smem_u32(const void* p) {
    uint32_t a;
    asm("{ .reg .u64 t; cvta.to.shared.u64 t, %1; cvt.u32.u64 %0, t; }" : "=r"(a) : "l"(p));
    return a;
}
#define SWZ(off) ((off) ^ (((off) >> 3) & 0x70))

__device__ __forceinline__ void ldsm4(uint32_t* r, uint32_t addr) {
    asm volatile("ldmatrix.sync.aligned.m8n8.x4.shared.b16 {%0,%1,%2,%3}, [%4];"
        : "=r"(r[0]), "=r"(r[1]), "=r"(r[2]), "=r"(r[3]) : "r"(addr));
}
__device__ __forceinline__ void mma_bf16(float* d, const uint32_t* a, const uint32_t* b) {
    asm volatile(
        "mma.sync.aligned.m16n8k16.row.col.f32.bf16.bf16.f32 "
        "{%0,%1,%2,%3}, {%4,%5,%6,%7}, {%8,%9}, {%0,%1,%2,%3};"
        : "+f"(d[0]), "+f"(d[1]), "+f"(d[2]), "+f"(d[3])
        : "r"(a[0]), "r"(a[1]), "r"(a[2]), "r"(a[3]), "r"(b[0]), "r"(b[1]));
}

// smem layout: per buffer 64KB: AH 16K | AL 16K | BH 16K | BL 16K; x2 buffers; then bias 512B
#define SBUF     65536
#define OFF_AH   0
#define OFF_AL   16384
#define OFF_BH   32768
#define OFF_BL   49152
#define OFF_BIAS 131072
#define SM_TOTAL (131072 + 512)

// ---------------- encoder GEMM: H = relu(X @ W_enc + b) via bf16x3 on mma.sync ----------------
// CTA tile 128x128, 256 threads (8 warps: 4 m x 2 n, warp tile 32x64), BK=64, double-buffered.
__global__ __launch_bounds__(256, 1)
void gemm_mma_kernel(const float* __restrict__ bias, float* __restrict__ H)
{
    extern __shared__ char smem[];
    const uint32_t sb = smem_u32(smem);
    const int tid  = threadIdx.x;
    const int wid  = tid >> 5, lane = tid & 31;
    const int m0   = blockIdx.y * 128;
    const int n0   = blockIdx.x * 128;
    const int m_off = (wid & 3) * 32;   // warp m offset
    const int n_off = (wid >> 2) * 64;  // warp n offset

    if (tid < 128) *(float*)(smem + OFF_BIAS + tid * 4) = bias[n0 + tid];

    float acc[2][8][4] = {};

#define ISSUE_STAGE(s) do {                                                          \
    const int k0_ = (s) * 64;                                                        \
    const uint32_t base_ = sb + ((s) & 1) * SBUF;                                    \
    _Pragma("unroll")                                                                \
    for (int i = 0; i < 4; i++) {                                                    \
        const int c = tid + i * 256;                                                 \
        const int row = c >> 3, c16 = c & 7;                                         \
        const uint32_t off = SWZ((uint32_t)(row * 128 + c16 * 16));                  \
        const size_t gA = (size_t)(m0 + row) * DIN + k0_ + c16 * 8;                  \
        const size_t gB = (size_t)(n0 + row) * DIN + k0_ + c16 * 8;                  \
        asm volatile("cp.async.cg.shared.global [%0], [%1], 16;"                     \
                     :: "r"(base_ + OFF_AH + off), "l"(g_Xh + gA) : "memory");       \
        asm volatile("cp.async.cg.shared.global [%0], [%1], 16;"                     \
                     :: "r"(base_ + OFF_AL + off), "l"(g_Xl + gA) : "memory");       \
        asm volatile("cp.async.cg.shared.global [%0], [%1], 16;"                     \
                     :: "r"(base_ + OFF_BH + off), "l"(g_Wh + gB) : "memory");       \
        asm volatile("cp.async.cg.shared.global [%0], [%1], 16;"                     \
                     :: "r"(base_ + OFF_BL + off), "l"(g_Wl + gB) : "memory");       \
    }                                                                                \
    asm volatile("cp.async.commit_group;" ::: "memory");                             \
} while (0)

    ISSUE_STAGE(0);

    const int NST = DIN / 64;  // 16
    for (int s = 0; s < NST; s++) {
        if (s + 1 < NST) {
            ISSUE_STAGE(s + 1);
            asm volatile("cp.async.wait_group 1;" ::: "memory");
        } else {
            asm volatile("cp.async.wait_group 0;" ::: "memory");
        }
        __syncthreads();

        const uint32_t base = sb + (s & 1) * SBUF;
        #pragma unroll
        for (int ks = 0; ks < 4; ks++) {
            const int kb = ks * 16;
            // A fragments (hi, lo) for 2 m16 tiles
            uint32_t ah[2][4], al[2][4];
            #pragma unroll
            for (int fm = 0; fm < 2; fm++) {
                const int row = m_off + fm * 16 + (lane & 15);
                const int col = kb + (lane >> 4) * 8;
                const uint32_t off = SWZ((uint32_t)(row * 128 + col * 2));
                ldsm4(ah[fm], base + OFF_AH + off);
                ldsm4(al[fm], base + OFF_AL + off);
            }
            // B fragments: 4 x4 loads per precision, each covers 2 n8 frags
            uint32_t bh[8][2], bl[8][2];
            #pragma unroll
            for (int p = 0; p < 4; p++) {
                const int nrow = n_off + p * 16 + (lane & 7) + ((lane >> 4) & 1) * 8;
                const int kcol = kb + ((lane >> 3) & 1) * 8;
                const uint32_t off = SWZ((uint32_t)(nrow * 128 + kcol * 2));
                uint32_t t[4];
                ldsm4(t, base + OFF_BH + off);
                bh[2 * p][0] = t[0]; bh[2 * p][1] = t[1];
                bh[2 * p + 1][0] = t[2]; bh[2 * p + 1][1] = t[3];
                ldsm4(t, base + OFF_BL + off);
                bl[2 * p][0] = t[0]; bl[2 * p][1] = t[1];
                bl[2 * p + 1][0] = t[2]; bl[2 * p + 1][1] = t[3];
            }
            #pragma unroll
            for (int fm = 0; fm < 2; fm++)
                #pragma unroll
                for (int fn = 0; fn < 8; fn++) {
                    mma_bf16(acc[fm][fn], ah[fm], bh[fn]);
                    mma_bf16(acc[fm][fn], ah[fm], bl[fn]);
                    mma_bf16(acc[fm][fn], al[fm], bh[fn]);
                }
        }
        __syncthreads();
    }
#undef ISSUE_STAGE

    // epilogue: +bias, relu, store (d frag: c0,c1 -> row lane>>2; c2,c3 -> row+8)
    const float* bs = (const float*)(smem + OFF_BIAS);
    #pragma unroll
    for (int fm = 0; fm < 2; fm++) {
        #pragma unroll
        for (int fn = 0; fn < 8; fn++) {
            const int nc = n_off + fn * 8 + (lane & 3) * 2;
            const float b0 = bs[nc], b1 = bs[nc + 1];
            #pragma unroll
            for (int half = 0; half < 2; half++) {
                const int m = m0 + m_off + fm * 16 + (lane >> 2) + half * 8;
                float2 o;
                o.x = fmaxf(acc[fm][fn][half * 2 + 0] + b0, 0.f);
                o.y = fmaxf(acc[fm][fn][half * 2 + 1] + b1, 0.f);
                *(float2*)(H + (size_t)m * DSAE + n0 + nc) = o;
            }
        }
    }
}

// ---------------- per-row top-32 radix select + fp64 boundary refinement ----------------
__global__ __launch_bounds__(256)
void topk_kernel(float* __restrict__ H,
                 const float* __restrict__ x, const float* __restrict__ Wenc)
{
    extern __shared__ uint32_t sh[];   // 16384 uints = 64KB
    __shared__ int hist[256];
    __shared__ unsigned s_prefix;
    __shared__ int s_need, s_cnteq;
    __shared__ int s_cnt, s_pos;
    __shared__ uint32_t tiemask[512];
    __shared__ int s_nc, s_nselband;
    __shared__ int cand_idx[NC_MAX];
    __shared__ double cand_ref[NC_MAX];
    __shared__ double dred[256];
    __shared__ unsigned long long s_chosen;

    const int row = blockIdx.x;
    const int tid = threadIdx.x;
    float* hrow = H + (size_t)row * DSAE;

    for (int i = tid; i < DSAE / 4; i += 256)
        ((uint4*)sh)[i] = ((const uint4*)hrow)[i];
    if (tid == 0) {
        s_prefix = 0u; s_need = TOPK; s_cnt = 0; s_pos = 0;
        s_nc = 0; s_nselband = 0; s_chosen = 0ull;
    }
    __syncthreads();

    for (int shift = 24; shift >= 0; shift -= 8) {
        hist[tid] = 0;
        __syncthreads();
        const uint32_t himask = (shift == 24) ? 0u : (0xFFFFFFFFu << (shift + 8));
        const uint32_t pfx = s_prefix;
        for (int i = tid; i < DSAE; i += 256) {
            uint32_t u = sh[i];
            if ((u & himask) == pfx)
                atomicAdd(&hist[(u >> shift) & 255], 1);
        }
        __syncthreads();
        if (tid == 0) {
            int need = s_need, above = 0, b = 255;
            for (; b > 0; b--) {
                if (above + hist[b] >= need) break;
                above += hist[b];
            }
            s_prefix |= ((unsigned)b) << shift;
            s_need = need - above;
            s_cnteq = hist[b];
        }
        __syncthreads();
    }

    const uint32_t T = s_prefix;
    const int r = s_need;
    const bool ties = (s_cnteq != r);
    const float Tf = __uint_as_float(T);

    if (ties) {
        for (int i = tid; i < 512; i += 256) tiemask[i] = 0u;
        __syncthreads();
        if (tid == 0) {
            int taken = 0;
            for (int i = 0; i < DSAE && taken < r; i++)
                if (sh[i] == T) { tiemask[i >> 5] |= 1u << (i & 31); taken++; }
        }
        __syncthreads();
    }

    bool refine = false;
    if (!ties) {
        for (int i = tid; i < DSAE; i += 256) {
            const uint32_t u = sh[i];
            const float v = __uint_as_float(u);
            const bool selbase = (u >= T);
            const bool band = selbase ? (v < Tf + BAND_EPS) : (v > Tf - BAND_EPS);
            if (band) {
                const int p = atomicAdd(&s_nc, 1);
                if (p < NC_MAX) cand_idx[p] = i;
                if (selbase) atomicAdd(&s_nselband, 1);
            }
        }
        __syncthreads();
        const int nc = s_nc, nsb = s_nselband;
        refine = (nc <= NC_MAX) && (nc > nsb) && (nsb > 0);

        if (refine) {
            for (int c = 0; c < nc; c++) {
                const int f = cand_idx[c];
                double p = 0.0;
                const float* xr = x + (size_t)row * DIN;
                for (int k = tid; k < DIN; k += 256)
                    p += (double)xr[k] * (double)Wenc[(size_t)k * DSAE + f];
                dred[tid] = p;
                __syncthreads();
                for (int s = 128; s > 0; s >>= 1) {
                    if (tid < s) dred[tid] += dred[tid + s];
                    __syncthreads();
                }
                if (tid == 0) cand_ref[c] = dred[0];
                __syncthreads();
            }
            if (tid == 0) {
                unsigned long long chosen = 0ull;
                for (int t = 0; t < nsb; t++) {
                    int best = -1;
                    for (int c = 0; c < nc; c++) {
                        if ((chosen >> c) & 1ull) continue;
                        if (best < 0 ||
                            cand_ref[c] > cand_ref[best] ||
                            (cand_ref[c] == cand_ref[best] && cand_idx[c] < cand_idx[best]))
                            best = c;
                    }
                    chosen |= 1ull << best;
                }
                s_chosen = chosen;
            }
            __syncthreads();
        }
    }
    const int nc_f = s_nc;
    const unsigned long long chosen_f = s_chosen;

    for (int i = tid; i < DSAE; i += 256) {
        const uint32_t u = sh[i];
        const float v = __uint_as_float(u);
        bool sel;
        if (ties) {
            if (u > T)       sel = true;
            else if (u == T) sel = ((tiemask[i >> 5] >> (i & 31)) & 1u) != 0;
            else             sel = false;
        } else if (refine) {
            const bool selbase = (u >= T);
            const bool band = selbase ? (v < Tf + BAND_EPS) : (v > Tf - BAND_EPS);
            if (band) {
                sel = false;
                for (int c = 0; c < nc_f; c++)
                    if (cand_idx[c] == i) { sel = ((chosen_f >> c) & 1ull) != 0; break; }
            } else {
                sel = selbase;
            }
        } else {
            sel = (u >= T);
        }
        hrow[i] = sel ? v : 0.0f;
        if (sel) {
            const int slot = atomicAdd(&s_cnt, 1);
            g_tk_idx[row * TOPK + slot] = i;
            g_tk_val[row * TOPK + slot] = v;
            if (u != 0u) atomicAdd(&s_pos, 1);
        }
    }
    __syncthreads();
    if (tid == 0) atomicAdd(&g_l0_sum, (float)s_pos);
}

// ---------------- decoder: x_hat = h_sparse @ W_dec + b_dec, + loss ----------------
__global__ __launch_bounds__(256)
void decoder_kernel(const float* __restrict__ x, const float* __restrict__ Wdec,
                    const float* __restrict__ bdec, float* __restrict__ xhat)
{
    __shared__ int   sidx[TOPK];
    __shared__ float sval[TOPK];
    __shared__ float red[256];

    const int row = blockIdx.x;
    const int tid = threadIdx.x;
    if (tid < TOPK) {
        sidx[tid] = g_tk_idx[row * TOPK + tid];
        sval[tid] = g_tk_val[row * TOPK + tid];
    }
    __syncthreads();

    const int c = tid * 4;
    float4 acc = *reinterpret_cast<const float4*>(&bdec[c]);
    #pragma unroll 4
    for (int j = 0; j < TOPK; j++) {
        const float v = sval[j];
        const float4 w = *reinterpret_cast<const float4*>(&Wdec[(size_t)sidx[j] * DIN + c]);
        acc.x += v * w.x;
        acc.y += v * w.y;
        acc.z += v * w.z;
        acc.w += v * w.w;
    }
    const float4 xv = *reinterpret_cast<const float4*>(&x[(size_t)row * DIN + c]);
    *reinterpret_cast<float4*>(&xhat[(size_t)row * DIN + c]) = acc;

    const float dx = acc.x - xv.x, dy = acc.y - xv.y;
    const float dz = acc.z - xv.z, dw = acc.w - xv.w;
    red[tid] = dx * dx + dy * dy + dz * dz + dw * dw;
    __syncthreads();
    for (int s = 128; s > 0; s >>= 1) {
        if (tid < s) red[tid] += red[tid + s];
        __syncthreads();
    }
    if (tid == 0) atomicAdd(&g_loss_sum, (double)red[0]);
}

__global__ void finalize_kernel(float* __restrict__ out_loss, float* __restrict__ out_l0)
{
    out_loss[0] = (float)(g_loss_sum / ((double)BATCH * (double)DIN));
    out_l0[0]   = g_l0_sum / (float)BATCH;
}

// ---------------- launch ----------------
extern "C" void kernel_launch(void* const* d_in, const int* in_sizes, int n_in,
                              void* d_out, int out_size)
{
    const float* x     = (const float*)d_in[0];
    const float* W_enc = (const float*)d_in[1];
    const float* b_enc = (const float*)d_in[2];
    const float* W_dec = (const float*)d_in[3];
    const float* b_dec = (const float*)d_in[4];

    float* out   = (float*)d_out;
    float* xhat  = out;
    float* H     = out + (size_t)BATCH * DIN;
    float* oloss = out + (size_t)BATCH * DIN + (size_t)BATCH * DSAE;
    float* ol0   = oloss + 1;

    (void)in_sizes; (void)n_in; (void)out_size;

    cudaFuncSetAttribute(topk_kernel,
                         cudaFuncAttributeMaxDynamicSharedMemorySize, DSAE * 4);
    cudaFuncSetAttribute(gemm_mma_kernel,
                         cudaFuncAttributeMaxDynamicSharedMemorySize, SM_TOTAL);

    init_kernel<<<1, 1>>>();

    splitx_kernel<<<(BATCH * DIN) / 256, 256>>>(x);
    dim3 wb(32, 8);
    splitw_kernel<<<dim3(DSAE / 32, DIN / 32), wb>>>(W_enc);

    dim3 gg(DSAE / 128, BATCH / 128);  // (128, 64)
    gemm_mma_kernel<<<gg, 256, SM_TOTAL>>>(b_enc, H);

    topk_kernel<<<BATCH, 256, DSAE * 4>>>(H, x, W_enc);

    decoder_kernel<<<BATCH, 256>>>(x, W_dec, b_dec, xhat);

    finalize_kernel<<<1, 1>>>(oloss, ol0);
}

// round 5
// speedup vs baseline: 3.4577x; 1.4471x over previous
#include <cuda_runtime.h>
#include <cuda_bf16.h>
#include <cstdint>

#define BATCH 8192
#define DIN   1024
#define DSAE  16384
#define TOPK  32
#define NC_MAX 64
#define BAND_EPS 1.5e-2f   // 6.5 sigma of hi*hi bf16 GEMM noise (sigma ~ 2.3e-3)

// ---------------- scratch (no allocations allowed) ----------------
__device__ int    g_tk_idx[BATCH * TOPK];
__device__ float  g_tk_val[BATCH * TOPK];
__device__ double g_loss_sum;
__device__ float  g_l0_sum;
__device__ __align__(1024) __nv_bfloat16 g_Xh[BATCH * DIN];
__device__ __align__(1024) __nv_bfloat16 g_Wh[(size_t)DSAE * DIN];  // W_enc^T bf16-hi
__device__ __align__(1024) float         g_WT[(size_t)DSAE * DIN];  // W_enc^T fp32

__global__ void init_kernel() {
    g_loss_sum = 0.0;
    g_l0_sum   = 0.0f;
}

// ---------------- prep: bf16 hi of x ----------------
__global__ __launch_bounds__(256)
void splitx_kernel(const float* __restrict__ x)
{
    const size_t i = (size_t)blockIdx.x * blockDim.x + threadIdx.x;
    g_Xh[i] = __float2bfloat16_rn(x[i]);
}

// ---------------- prep: transpose W_enc -> fp32 W^T and bf16-hi W^T ----------------
__global__ __launch_bounds__(256)
void splitw_kernel(const float* __restrict__ W)
{
    __shared__ float t[32][33];
    const int n0 = blockIdx.x * 32, k0 = blockIdx.y * 32;
    const int tx = threadIdx.x, ty = threadIdx.y;  // 32 x 8
    #pragma unroll
    for (int i = 0; i < 32; i += 8)
        t[ty + i][tx] = W[(size_t)(k0 + ty + i) * DSAE + n0 + tx];
    __syncthreads();
    #pragma unroll
    for (int i = 0; i < 32; i += 8) {
        const float v = t[tx][ty + i];  // = W[k0+tx][n0+ty+i]
        const size_t o = (size_t)(n0 + ty + i) * DIN + k0 + tx;
        g_Wh[o] = __float2bfloat16_rn(v);
        g_WT[o] = v;
    }
}

// ---------------- helpers ----------------
__device__ __forceinline__ uint32_t smem_u32(const void* p) {
    uint32_t a;
    asm("{ .reg .u64 t; cvta.to.shared.u64 t, %1; cvt.u32.u64 %0, t; }" : "=r"(a) : "l"(p));
    return a;
}
#define SWZ(off) ((off) ^ (((off) >> 3) & 0x70))

__device__ __forceinline__ void ldsm4(uint32_t* r, uint32_t addr) {
    asm volatile("ldmatrix.sync.aligned.m8n8.x4.shared.b16 {%0,%1,%2,%3}, [%4];"
        : "=r"(r[0]), "=r"(r[1]), "=r"(r[2]), "=r"(r[3]) : "r"(addr));
}
__device__ __forceinline__ void mma_bf16(float* d, const uint32_t* a, const uint32_t* b) {
    asm volatile(
        "mma.sync.aligned.m16n8k16.row.col.f32.bf16.bf16.f32 "
        "{%0,%1,%2,%3}, {%4,%5,%6,%7}, {%8,%9}, {%0,%1,%2,%3};"
        : "+f"(d[0]), "+f"(d[1]), "+f"(d[2]), "+f"(d[3])
        : "r"(a[0]), "r"(a[1]), "r"(a[2]), "r"(a[3]), "r"(b[0]), "r"(b[1]));
}

// smem: per buffer 32KB (AH 16K | BH 16K), x2 buffers, then bias 512B
#define SBUF     32768
#define OFF_AH   0
#define OFF_BH   16384
#define OFF_BIAS 65536
#define SM_TOTAL (65536 + 512)

// ---------------- encoder GEMM (approx): H = relu(Xh @ Wh^T + b) ----------------
// CTA tile 128x128, 256 threads (8 warps: 4 m x 2 n, warp tile 32x64), BK=64, double-buffered.
__global__ __launch_bounds__(256, 2)
void gemm_mma_kernel(const float* __restrict__ bias, float* __restrict__ H)
{
    extern __shared__ char smem[];
    const uint32_t sb = smem_u32(smem);
    const int tid  = threadIdx.x;
    const int wid  = tid >> 5, lane = tid & 31;
    const int m0   = blockIdx.y * 128;
    const int n0   = blockIdx.x * 128;
    const int m_off = (wid & 3) * 32;
    const int n_off = (wid >> 2) * 64;

    if (tid < 128) *(float*)(smem + OFF_BIAS + tid * 4) = bias[n0 + tid];

    float acc[2][8][4] = {};

#define ISSUE_STAGE(s) do {                                                          \
    const int k0_ = (s) * 64;                                                        \
    const uint32_t base_ = sb + ((s) & 1) * SBUF;                                    \
    _Pragma("unroll")                                                                \
    for (int i = 0; i < 4; i++) {                                                    \
        const int c = tid + i * 256;                                                 \
        const int row = c >> 3, c16 = c & 7;                                         \
        const uint32_t off = SWZ((uint32_t)(row * 128 + c16 * 16));                  \
        const size_t gA = (size_t)(m0 + row) * DIN + k0_ + c16 * 8;                  \
        const size_t gB = (size_t)(n0 + row) * DIN + k0_ + c16 * 8;                  \
        asm volatile("cp.async.cg.shared.global [%0], [%1], 16;"                     \
                     :: "r"(base_ + OFF_AH + off), "l"(g_Xh + gA) : "memory");       \
        asm volatile("cp.async.cg.shared.global [%0], [%1], 16;"                     \
                     :: "r"(base_ + OFF_BH + off), "l"(g_Wh + gB) : "memory");       \
    }                                                                                \
    asm volatile("cp.async.commit_group;" ::: "memory");                             \
} while (0)

    ISSUE_STAGE(0);

    const int NST = DIN / 64;  // 16
    for (int s = 0; s < NST; s++) {
        if (s + 1 < NST) {
            ISSUE_STAGE(s + 1);
            asm volatile("cp.async.wait_group 1;" ::: "memory");
        } else {
            asm volatile("cp.async.wait_group 0;" ::: "memory");
        }
        __syncthreads();

        const uint32_t base = sb + (s & 1) * SBUF;
        #pragma unroll
        for (int ks = 0; ks < 4; ks++) {
            const int kb = ks * 16;
            uint32_t ah[2][4];
            #pragma unroll
            for (int fm = 0; fm < 2; fm++) {
                const int row = m_off + fm * 16 + (lane & 15);
                const int col = kb + (lane >> 4) * 8;
                const uint32_t off = SWZ((uint32_t)(row * 128 + col * 2));
                ldsm4(ah[fm], base + OFF_AH + off);
            }
            uint32_t bh[8][2];
            #pragma unroll
            for (int p = 0; p < 4; p++) {
                const int nrow = n_off + p * 16 + (lane & 7) + ((lane >> 4) & 1) * 8;
                const int kcol = kb + ((lane >> 3) & 1) * 8;
                const uint32_t off = SWZ((uint32_t)(nrow * 128 + kcol * 2));
                uint32_t t[4];
                ldsm4(t, base + OFF_BH + off);
                bh[2 * p][0] = t[0]; bh[2 * p][1] = t[1];
                bh[2 * p + 1][0] = t[2]; bh[2 * p + 1][1] = t[3];
            }
            #pragma unroll
            for (int fm = 0; fm < 2; fm++)
                #pragma unroll
                for (int fn = 0; fn < 8; fn++)
                    mma_bf16(acc[fm][fn], ah[fm], bh[fn]);
        }
        __syncthreads();
    }
#undef ISSUE_STAGE

    const float* bs = (const float*)(smem + OFF_BIAS);
    #pragma unroll
    for (int fm = 0; fm < 2; fm++) {
        #pragma unroll
        for (int fn = 0; fn < 8; fn++) {
            const int nc = n_off + fn * 8 + (lane & 3) * 2;
            const float b0 = bs[nc], b1 = bs[nc + 1];
            #pragma unroll
            for (int half = 0; half < 2; half++) {
                const int m = m0 + m_off + fm * 16 + (lane >> 2) + half * 8;
                float2 o;
                o.x = fmaxf(acc[fm][fn][half * 2 + 0] + b0, 0.f);
                o.y = fmaxf(acc[fm][fn][half * 2 + 1] + b1, 0.f);
                *(float2*)(H + (size_t)m * DSAE + n0 + nc) = o;
            }
        }
    }
}

// ---------------- per-row top-32 radix select + fp64 boundary refinement ----------------
__global__ __launch_bounds__(256)
void topk_kernel(float* __restrict__ H, const float* __restrict__ x)
{
    extern __shared__ uint32_t sh[];   // 16384 uints = 64KB
    __shared__ int hist[256];
    __shared__ unsigned s_prefix;
    __shared__ int s_need, s_cnteq;
    __shared__ int s_cnt, s_pos;
    __shared__ uint32_t tiemask[512];
    __shared__ int s_nc, s_nselband;
    __shared__ int cand_idx[NC_MAX];
    __shared__ double cand_ref[NC_MAX];
    __shared__ double dred[256];
    __shared__ unsigned long long s_chosen;

    const int row = blockIdx.x;
    const int tid = threadIdx.x;
    float* hrow = H + (size_t)row * DSAE;

    for (int i = tid; i < DSAE / 4; i += 256)
        ((uint4*)sh)[i] = ((const uint4*)hrow)[i];
    if (tid == 0) {
        s_prefix = 0u; s_need = TOPK; s_cnt = 0; s_pos = 0;
        s_nc = 0; s_nselband = 0; s_chosen = 0ull;
    }
    __syncthreads();

    for (int shift = 24; shift >= 0; shift -= 8) {
        hist[tid] = 0;
        __syncthreads();
        const uint32_t himask = (shift == 24) ? 0u : (0xFFFFFFFFu << (shift + 8));
        const uint32_t pfx = s_prefix;
        for (int i = tid; i < DSAE; i += 256) {
            uint32_t u = sh[i];
            if ((u & himask) == pfx)
                atomicAdd(&hist[(u >> shift) & 255], 1);
        }
        __syncthreads();
        if (tid == 0) {
            int need = s_need, above = 0, b = 255;
            for (; b > 0; b--) {
                if (above + hist[b] >= need) break;
                above += hist[b];
            }
            s_prefix |= ((unsigned)b) << shift;
            s_need = need - above;
            s_cnteq = hist[b];
        }
        __syncthreads();
    }

    const uint32_t T = s_prefix;
    const int r = s_need;
    const bool ties = (s_cnteq != r);
    const float Tf = __uint_as_float(T);

    if (ties) {
        for (int i = tid; i < 512; i += 256) tiemask[i] = 0u;
        __syncthreads();
        if (tid == 0) {
            int taken = 0;
            for (int i = 0; i < DSAE && taken < r; i++)
                if (sh[i] == T) { tiemask[i >> 5] |= 1u << (i & 31); taken++; }
        }
        __syncthreads();
    }

    bool refine = false;
    if (!ties) {
        for (int i = tid; i < DSAE; i += 256) {
            const uint32_t u = sh[i];
            const float v = __uint_as_float(u);
            const bool selbase = (u >= T);
            const bool band = selbase ? (v < Tf + BAND_EPS) : (v > Tf - BAND_EPS);
            if (band) {
                const int p = atomicAdd(&s_nc, 1);
                if (p < NC_MAX) cand_idx[p] = i;
                if (selbase) atomicAdd(&s_nselband, 1);
            }
        }
        __syncthreads();
        const int nc = s_nc, nsb = s_nselband;
        refine = (nc <= NC_MAX) && (nc > nsb) && (nsb > 0);

        if (refine) {
            for (int c = 0; c < nc; c++) {
                const int f = cand_idx[c];
                double p = 0.0;
                const float* xr = x + (size_t)row * DIN;
                const float* wr = g_WT + (size_t)f * DIN;
                for (int k = tid; k < DIN; k += 256)
                    p += (double)xr[k] * (double)wr[k];
                dred[tid] = p;
                __syncthreads();
                for (int s = 128; s > 0; s >>= 1) {
                    if (tid < s) dred[tid] += dred[tid + s];
                    __syncthreads();
                }
                if (tid == 0) cand_ref[c] = dred[0];
                __syncthreads();
            }
            if (tid == 0) {
                unsigned long long chosen = 0ull;
                for (int t = 0; t < nsb; t++) {
                    int best = -1;
                    for (int c = 0; c < nc; c++) {
                        if ((chosen >> c) & 1ull) continue;
                        if (best < 0 ||
                            cand_ref[c] > cand_ref[best] ||
                            (cand_ref[c] == cand_ref[best] && cand_idx[c] < cand_idx[best]))
                            best = c;
                    }
                    chosen |= 1ull << best;
                }
                s_chosen = chosen;
            }
            __syncthreads();
        }
    }
    const int nc_f = s_nc;
    const unsigned long long chosen_f = s_chosen;

    for (int i = tid; i < DSAE; i += 256) {
        const uint32_t u = sh[i];
        const float v = __uint_as_float(u);
        bool sel;
        if (ties) {
            if (u > T)       sel = true;
            else if (u == T) sel = ((tiemask[i >> 5] >> (i & 31)) & 1u) != 0;
            else             sel = false;
        } else if (refine) {
            const bool selbase = (u >= T);
            const bool band = selbase ? (v < Tf + BAND_EPS) : (v > Tf - BAND_EPS);
            if (band) {
                sel = false;
                for (int c = 0; c < nc_f; c++)
                    if (cand_idx[c] == i) { sel = ((chosen_f >> c) & 1ull) != 0; break; }
            } else {
                sel = selbase;
            }
        } else {
            sel = (u >= T);
        }
        hrow[i] = sel ? v : 0.0f;
        if (sel) {
            const int slot = atomicAdd(&s_cnt, 1);
            g_tk_idx[row * TOPK + slot] = i;
            g_tk_val[row * TOPK + slot] = v;
            if (u != 0u) atomicAdd(&s_pos, 1);
        }
    }
    __syncthreads();
    if (tid == 0) atomicAdd(&g_l0_sum, (float)s_pos);
}

// ---------------- value-fix: exact fp32 pre_acts for the 32 selected features ----------------
// One CTA per row; warp w handles slots 4w..4w+3; 1024-dot per slot via lane-split + shuffle.
__global__ __launch_bounds__(256)
void valuefix_kernel(const float* __restrict__ x, const float* __restrict__ benc,
                     float* __restrict__ H)
{
    const int row  = blockIdx.x;
    const int wid  = threadIdx.x >> 5, lane = threadIdx.x & 31;
    const float* xr = x + (size_t)row * DIN;

    #pragma unroll
    for (int j = 0; j < 4; j++) {
        const int slot = wid * 4 + j;
        const int f = g_tk_idx[row * TOPK + slot];
        const float* wr = g_WT + (size_t)f * DIN;
        float s = 0.f;
        #pragma unroll 8
        for (int k = lane; k < DIN; k += 32)
            s = fmaf(xr[k], wr[k], s);
        #pragma unroll
        for (int o = 16; o > 0; o >>= 1)
            s += __shfl_xor_sync(0xFFFFFFFFu, s, o);
        if (lane == 0) {
            const float v = fmaxf(s + benc[f], 0.f);
            H[(size_t)row * DSAE + f] = v;
            g_tk_val[row * TOPK + slot] = v;
        }
    }
}

// ---------------- decoder: x_hat = h_sparse @ W_dec + b_dec, + loss ----------------
__global__ __launch_bounds__(256)
void decoder_kernel(const float* __restrict__ x, const float* __restrict__ Wdec,
                    const float* __restrict__ bdec, float* __restrict__ xhat)
{
    __shared__ int   sidx[TOPK];
    __shared__ float sval[TOPK];
    __shared__ float red[256];

    const int row = blockIdx.x;
    const int tid = threadIdx.x;
    if (tid < TOPK) {
        sidx[tid] = g_tk_idx[row * TOPK + tid];
        sval[tid] = g_tk_val[row * TOPK + tid];
    }
    __syncthreads();

    const int c = tid * 4;
    float4 acc = *reinterpret_cast<const float4*>(&bdec[c]);
    #pragma unroll 4
    for (int j = 0; j < TOPK; j++) {
        const float v = sval[j];
        const float4 w = *reinterpret_cast<const float4*>(&Wdec[(size_t)sidx[j] * DIN + c]);
        acc.x += v * w.x;
        acc.y += v * w.y;
        acc.z += v * w.z;
        acc.w += v * w.w;
    }
    const float4 xv = *reinterpret_cast<const float4*>(&x[(size_t)row * DIN + c]);
    *reinterpret_cast<float4*>(&xhat[(size_t)row * DIN + c]) = acc;

    const float dx = acc.x - xv.x, dy = acc.y - xv.y;
    const float dz = acc.z - xv.z, dw = acc.w - xv.w;
    red[tid] = dx * dx + dy * dy + dz * dz + dw * dw;
    __syncthreads();
    for (int s = 128; s > 0; s >>= 1) {
        if (tid < s) red[tid] += red[tid + s];
        __syncthreads();
    }
    if (tid == 0) atomicAdd(&g_loss_sum, (double)red[0]);
}

__global__ void finalize_kernel(float* __restrict__ out_loss, float* __restrict__ out_l0)
{
    out_loss[0] = (float)(g_loss_sum / ((double)BATCH * (double)DIN));
    out_l0[0]   = g_l0_sum / (float)BATCH;
}

// ---------------- launch ----------------
extern "C" void kernel_launch(void* const* d_in, const int* in_sizes, int n_in,
                              void* d_out, int out_size)
{
    const float* x     = (const float*)d_in[0];
    const float* W_enc = (const float*)d_in[1];
    const float* b_enc = (const float*)d_in[2];
    const float* W_dec = (const float*)d_in[3];
    const float* b_dec = (const float*)d_in[4];

    float* out   = (float*)d_out;
    float* xhat  = out;
    float* H     = out + (size_t)BATCH * DIN;
    float* oloss = out + (size_t)BATCH * DIN + (size_t)BATCH * DSAE;
    float* ol0   = oloss + 1;

    (void)in_sizes; (void)n_in; (void)out_size;

    cudaFuncSetAttribute(topk_kernel,
                         cudaFuncAttributeMaxDynamicSharedMemorySize, DSAE * 4);
    cudaFuncSetAttribute(gemm_mma_kernel,
                         cudaFuncAttributeMaxDynamicSharedMemorySize, SM_TOTAL);

    init_kernel<<<1, 1>>>();

    splitx_kernel<<<(BATCH * DIN) / 256, 256>>>(x);
    dim3 wb(32, 8);
    splitw_kernel<<<dim3(DSAE / 32, DIN / 32), wb>>>(W_enc);

    dim3 gg(DSAE / 128, BATCH / 128);  // (128, 64)
    gemm_mma_kernel<<<gg, 256, SM_TOTAL>>>(b_enc, H);

    topk_kernel<<<BATCH, 256, DSAE * 4>>>(H, x);

    valuefix_kernel<<<BATCH, 256>>>(x, b_enc, H);

    decoder_kernel<<<BATCH, 256>>>(x, W_dec, b_dec, xhat);

    finalize_kernel<<<1, 1>>>(oloss, ol0);
}

// round 6
// speedup vs baseline: 6.2442x; 1.8059x over previous
#include <cuda_runtime.h>
#include <cuda_bf16.h>
#include <cstdint>

#define BATCH 8192
#define DIN   1024
#define DSAE  16384
#define TOPK  32
#define CAP   768          // candidate buffer per row
#define NB_MAX 64          // max band members for fp64 refinement
#define BAND  2.0e-2f      // ambiguity band (pairwise approx noise sigma ~3.2e-3)
#define FB_MAX 128         // fallback scratch rows

// ---------------- scratch (no allocations allowed) ----------------
__device__ int    g_tk_idx[BATCH * TOPK];
__device__ float  g_tk_val[BATCH * TOPK];
__device__ double g_loss_sum;
__device__ float  g_l0_sum;
__device__ float  g_T0[BATCH];
__device__ int    g_cnt[BATCH];
__device__ int    g_flag[BATCH];
__device__ int    g_fbn;
__device__ __align__(16)   uint2 g_cand[(size_t)BATCH * CAP];       // (val bits, col)
__device__ __align__(16)   double g_fbv[(size_t)FB_MAX * DSAE];     // fallback values
__device__ __align__(1024) __nv_bfloat16 g_Xh[BATCH * DIN];
__device__ __align__(1024) __nv_bfloat16 g_Wh[(size_t)DSAE * DIN];  // W_enc^T bf16
__device__ __align__(1024) float         g_WT[(size_t)DSAE * DIN];  // W_enc^T fp32

__global__ void init_kernel() {
    const int i = blockIdx.x * blockDim.x + threadIdx.x;
    if (i < BATCH) { g_cnt[i] = 0; g_flag[i] = 0; }
    if (i == 0) { g_loss_sum = 0.0; g_l0_sum = 0.0f; g_fbn = 0; }
}

// ---------------- prep: bf16 x + per-row candidate threshold ----------------
__global__ __launch_bounds__(256)
void splitx_kernel(const float* __restrict__ x)
{
    const int row  = blockIdx.x * 8 + (threadIdx.x >> 5);
    const int lane = threadIdx.x & 31;
    const float* xr = x + (size_t)row * DIN;
    __nv_bfloat16* dr = g_Xh + (size_t)row * DIN;
    float ss = 0.f;
    #pragma unroll
    for (int i = 0; i < 8; i++) {
        const int k = lane * 4 + i * 128;
        const float4 v = *(const float4*)(xr + k);
        ss += v.x * v.x + v.y * v.y + v.z * v.z + v.w * v.w;
        dr[k + 0] = __float2bfloat16_rn(v.x);
        dr[k + 1] = __float2bfloat16_rn(v.y);
        dr[k + 2] = __float2bfloat16_rn(v.z);
        dr[k + 3] = __float2bfloat16_rn(v.w);
    }
    #pragma unroll
    for (int o = 16; o > 0; o >>= 1) ss += __shfl_xor_sync(0xFFFFFFFFu, ss, o);
    if (lane == 0) g_T0[row] = 2.40f * 0.04419417f * sqrtf(ss);
}

// ---------------- prep: transpose W_enc -> fp32 W^T and bf16 W^T ----------------
__global__ __launch_bounds__(256)
void splitw_kernel(const float* __restrict__ W)
{
    __shared__ float t[32][33];
    const int n0 = blockIdx.x * 32, k0 = blockIdx.y * 32;
    const int tx = threadIdx.x, ty = threadIdx.y;  // 32 x 8
    #pragma unroll
    for (int i = 0; i < 32; i += 8)
        t[ty + i][tx] = W[(size_t)(k0 + ty + i) * DSAE + n0 + tx];
    __syncthreads();
    #pragma unroll
    for (int i = 0; i < 32; i += 8) {
        const float v = t[tx][ty + i];
        const size_t o = (size_t)(n0 + ty + i) * DIN + k0 + tx;
        g_Wh[o] = __float2bfloat16_rn(v);
        g_WT[o] = v;
    }
}

// ---------------- helpers ----------------
__device__ __forceinline__ uint32_t smem_u32(const void* p) {
    uint32_t a;
    asm("{ .reg .u64 t; cvta.to.shared.u64 t, %1; cvt.u32.u64 %0, t; }" : "=r"(a) : "l"(p));
    return a;
}
#define SWZ(off) ((off) ^ (((off) >> 3) & 0x70))

__device__ __forceinline__ void ldsm4(uint32_t* r, uint32_t addr) {
    asm volatile("ldmatrix.sync.aligned.m8n8.x4.shared.b16 {%0,%1,%2,%3}, [%4];"
        : "=r"(r[0]), "=r"(r[1]), "=r"(r[2]), "=r"(r[3]) : "r"(addr));
}
__device__ __forceinline__ void mma_bf16(float* d, const uint32_t* a, const uint32_t* b) {
    asm volatile(
        "mma.sync.aligned.m16n8k16.row.col.f32.bf16.bf16.f32 "
        "{%0,%1,%2,%3}, {%4,%5,%6,%7}, {%8,%9}, {%0,%1,%2,%3};"
        : "+f"(d[0]), "+f"(d[1]), "+f"(d[2]), "+f"(d[3])
        : "r"(a[0]), "r"(a[1]), "r"(a[2]), "r"(a[3]), "r"(b[0]), "r"(b[1]));
}

#define SBUF     32768
#define OFF_AH   0
#define OFF_BH   16384
#define OFF_BIAS 65536
#define OFF_T0   66048
#define SM_TOTAL 66560

// ---------------- encoder GEMM: zeros into h_sparse + candidate extraction ----------------
__global__ __launch_bounds__(256, 2)
void gemm_mma_kernel(const float* __restrict__ bias, float* __restrict__ H)
{
    extern __shared__ char smem[];
    const uint32_t sb = smem_u32(smem);
    const int tid  = threadIdx.x;
    const int wid  = tid >> 5, lane = tid & 31;
    const int m0   = blockIdx.y * 128;
    const int n0   = blockIdx.x * 128;
    const int m_off = (wid & 3) * 32;
    const int n_off = (wid >> 2) * 64;

    if (tid < 128) {
        *(float*)(smem + OFF_BIAS + tid * 4) = bias[n0 + tid];
        *(float*)(smem + OFF_T0   + tid * 4) = g_T0[m0 + tid];
    }

    float acc[2][8][4] = {};

#define ISSUE_STAGE(s) do {                                                          \
    const int k0_ = (s) * 64;                                                        \
    const uint32_t base_ = sb + ((s) & 1) * SBUF;                                    \
    _Pragma("unroll")                                                                \
    for (int i = 0; i < 4; i++) {                                                    \
        const int c = tid + i * 256;                                                 \
        const int row = c >> 3, c16 = c & 7;                                         \
        const uint32_t off = SWZ((uint32_t)(row * 128 + c16 * 16));                  \
        const size_t gA = (size_t)(m0 + row) * DIN + k0_ + c16 * 8;                  \
        const size_t gB = (size_t)(n0 + row) * DIN + k0_ + c16 * 8;                  \
        asm volatile("cp.async.cg.shared.global [%0], [%1], 16;"                     \
                     :: "r"(base_ + OFF_AH + off), "l"(g_Xh + gA) : "memory");       \
        asm volatile("cp.async.cg.shared.global [%0], [%1], 16;"                     \
                     :: "r"(base_ + OFF_BH + off), "l"(g_Wh + gB) : "memory");       \
    }                                                                                \
    asm volatile("cp.async.commit_group;" ::: "memory");                             \
} while (0)

    ISSUE_STAGE(0);

    const int NST = DIN / 64;  // 16
    for (int s = 0; s < NST; s++) {
        if (s + 1 < NST) {
            ISSUE_STAGE(s + 1);
            asm volatile("cp.async.wait_group 1;" ::: "memory");
        } else {
            asm volatile("cp.async.wait_group 0;" ::: "memory");
        }
        __syncthreads();

        const uint32_t base = sb + (s & 1) * SBUF;
        #pragma unroll
        for (int ks = 0; ks < 4; ks++) {
            const int kb = ks * 16;
            uint32_t ah[2][4];
            #pragma unroll
            for (int fm = 0; fm < 2; fm++) {
                const int row = m_off + fm * 16 + (lane & 15);
                const int col = kb + (lane >> 4) * 8;
                const uint32_t off = SWZ((uint32_t)(row * 128 + col * 2));
                ldsm4(ah[fm], base + OFF_AH + off);
            }
            uint32_t bh[8][2];
            #pragma unroll
            for (int p = 0; p < 4; p++) {
                const int nrow = n_off + p * 16 + (lane & 7) + ((lane >> 4) & 1) * 8;
                const int kcol = kb + ((lane >> 3) & 1) * 8;
                const uint32_t off = SWZ((uint32_t)(nrow * 128 + kcol * 2));
                uint32_t t[4];
                ldsm4(t, base + OFF_BH + off);
                bh[2 * p][0] = t[0]; bh[2 * p][1] = t[1];
                bh[2 * p + 1][0] = t[2]; bh[2 * p + 1][1] = t[3];
            }
            #pragma unroll
            for (int fm = 0; fm < 2; fm++)
                #pragma unroll
                for (int fn = 0; fn < 8; fn++)
                    mma_bf16(acc[fm][fn], ah[fm], bh[fn]);
        }
        __syncthreads();
    }
#undef ISSUE_STAGE

    // epilogue: zero-fill h_sparse tile; candidates (v > T0[row]) -> global list
    const float* bs = (const float*)(smem + OFF_BIAS);
    const float* t0 = (const float*)(smem + OFF_T0);
    #pragma unroll
    for (int fm = 0; fm < 2; fm++) {
        #pragma unroll
        for (int fn = 0; fn < 8; fn++) {
            const int nc = n_off + fn * 8 + (lane & 3) * 2;
            const float b0 = bs[nc], b1 = bs[nc + 1];
            #pragma unroll
            for (int half = 0; half < 2; half++) {
                const int lr = m_off + fm * 16 + (lane >> 2) + half * 8;
                const int m = m0 + lr;
                const float v0 = acc[fm][fn][half * 2 + 0] + b0;
                const float v1 = acc[fm][fn][half * 2 + 1] + b1;
                *(float2*)(H + (size_t)m * DSAE + n0 + nc) = make_float2(0.f, 0.f);
                const float th = t0[lr];
                if (v0 > th) {
                    const int p = atomicAdd(&g_cnt[m], 1);
                    if (p < CAP) g_cand[(size_t)m * CAP + p] =
                        make_uint2(__float_as_uint(v0), (unsigned)(n0 + nc));
                }
                if (v1 > th) {
                    const int p = atomicAdd(&g_cnt[m], 1);
                    if (p < CAP) g_cand[(size_t)m * CAP + p] =
                        make_uint2(__float_as_uint(v1), (unsigned)(n0 + nc + 1));
                }
            }
        }
    }
}

// ---------------- select: rank candidates, fp64 band refine, exact fp32 values ----------------
__global__ __launch_bounds__(128)
void select_kernel(const float* __restrict__ x, const float* __restrict__ benc,
                   float* __restrict__ H)
{
    __shared__ float sval[CAP];
    __shared__ int   sidx[CAP];
    __shared__ unsigned char ssel[CAP];
    __shared__ int   stop[TOPK];
    __shared__ int   s_band[NB_MAX];
    __shared__ double s_exact[NB_MAX];
    __shared__ double dred[128];
    __shared__ int   s_nb, s_nsb, s_l0;
    __shared__ int   s_final[TOPK];
    __shared__ unsigned long long s_chosen;

    const int row = blockIdx.x;
    const int tid = threadIdx.x;
    const int n = g_cnt[row];
    if (n < TOPK || n > CAP) { if (tid == 0) g_flag[row] = 1; return; }

    for (int i = tid; i < n; i += 128) {
        const uint2 c = g_cand[(size_t)row * CAP + i];
        sval[i] = __uint_as_float(c.x);
        sidx[i] = (int)c.y;
    }
    if (tid == 0) { s_nb = 0; s_nsb = 0; s_l0 = 0; s_chosen = 0ull; }
    __syncthreads();

    // exact rank by (value desc, idx asc) — strict total order
    for (int i = tid; i < n; i += 128) {
        const float vi = sval[i]; const int ii = sidx[i];
        int r = 0;
        for (int j = 0; j < n; j++) {
            const float vj = sval[j];
            r += (vj > vi) || (vj == vi && sidx[j] < ii);
        }
        ssel[i] = (r < TOPK);
        if (r < TOPK) stop[r] = i;
    }
    __syncthreads();

    const float v32 = sval[stop[TOPK - 1]];

    // band collection
    for (int i = tid; i < n; i += 128) {
        if (fabsf(sval[i] - v32) <= BAND) {
            const int p = atomicAdd(&s_nb, 1);
            if (p < NB_MAX) s_band[p] = i;
            if (ssel[i]) atomicAdd(&s_nsb, 1);
        }
    }
    __syncthreads();
    const int nb = s_nb, nsb = s_nsb;
    if (nb > NB_MAX) { if (tid == 0) g_flag[row] = 1; return; }

    const bool refine = (nb > nsb);
    if (refine) {
        const float* xr = x + (size_t)row * DIN;
        for (int c = 0; c < nb; c++) {
            const float* wr = g_WT + (size_t)sidx[s_band[c]] * DIN;
            double p = 0.0;
            for (int k = tid; k < DIN; k += 128)
                p += (double)xr[k] * (double)wr[k];
            dred[tid] = p;
            __syncthreads();
            for (int s = 64; s > 0; s >>= 1) {
                if (tid < s) dred[tid] += dred[tid + s];
                __syncthreads();
            }
            if (tid == 0) s_exact[c] = dred[0];
            __syncthreads();
        }
    }
    if (tid == 0) {
        int cnt = 0;
        if (refine) {
            for (int r = 0; r < TOPK; r++) {
                const int i = stop[r];
                if (fabsf(sval[i] - v32) > BAND) s_final[cnt++] = i;
            }
            unsigned long long chosen = 0ull;
            for (int t = 0; t < nsb; t++) {
                int best = -1;
                for (int c = 0; c < nb; c++) {
                    if ((chosen >> c) & 1ull) continue;
                    if (best < 0 ||
                        s_exact[c] > s_exact[best] ||
                        (s_exact[c] == s_exact[best] &&
                         sidx[s_band[c]] < sidx[s_band[best]]))
                        best = c;
                }
                chosen |= 1ull << best;
                s_final[cnt++] = s_band[best];
            }
        } else {
            for (int r = 0; r < TOPK; r++) s_final[r] = stop[r];
        }
    }
    __syncthreads();

    // exact fp32 values for the 32 selected (warp per slot-group of 8)
    const int wid = tid >> 5, lane = tid & 31;
    const float* xr = x + (size_t)row * DIN;
    #pragma unroll
    for (int j = 0; j < 8; j++) {
        const int slot = wid * 8 + j;
        const int f = sidx[s_final[slot]];
        const float* wr = g_WT + (size_t)f * DIN;
        float s = 0.f;
        #pragma unroll 8
        for (int k = lane; k < DIN; k += 32)
            s = fmaf(xr[k], wr[k], s);
        #pragma unroll
        for (int o = 16; o > 0; o >>= 1)
            s += __shfl_xor_sync(0xFFFFFFFFu, s, o);
        if (lane == 0) {
            const float v = fmaxf(s + benc[f], 0.f);
            g_tk_idx[row * TOPK + slot] = f;
            g_tk_val[row * TOPK + slot] = v;
            H[(size_t)row * DSAE + f] = v;
            if (v > 0.f) atomicAdd(&s_l0, 1);
        }
    }
    __syncthreads();
    if (tid == 0) atomicAdd(&g_l0_sum, (float)s_l0);
}

// ---------------- fallback: exact fp64 full-row top-k (flag-driven, ~never runs) ----------------
__global__ __launch_bounds__(256)
void fallback_kernel(const float* __restrict__ x, const float* __restrict__ benc,
                     float* __restrict__ H)
{
    const int row = blockIdx.x;
    if (!g_flag[row]) return;
    const int tid = threadIdx.x;
    __shared__ int s_slot;
    __shared__ double s_bv[256];
    __shared__ int    s_bi[256];
    __shared__ int    s_l0;
    if (tid == 0) { s_slot = atomicAdd(&g_fbn, 1); s_l0 = 0; }
    __syncthreads();
    const int slot = s_slot;
    double* vrow = (slot < FB_MAX) ? (g_fbv + (size_t)slot * DSAE) : nullptr;
    const float* xr = x + (size_t)row * DIN;

    if (vrow) {
        for (int f = tid; f < DSAE; f += 256) {
            const float* wr = g_WT + (size_t)f * DIN;
            double s = 0.0;
            for (int k = 0; k < DIN; k++) s += (double)xr[k] * (double)wr[k];
            vrow[f] = s + (double)benc[f];
        }
        __syncthreads();
    }

    double pv = 1e300; int pi = -1;
    for (int t = 0; t < TOPK; t++) {
        double bv = -1e300; int bi = -1;
        for (int f = tid; f < DSAE; f += 256) {
            double v;
            if (vrow) v = vrow[f];
            else {
                const float* wr = g_WT + (size_t)f * DIN;
                double s = 0.0;
                for (int k = 0; k < DIN; k++) s += (double)xr[k] * (double)wr[k];
                v = s + (double)benc[f];
            }
            const bool after = (v < pv) || (v == pv && f > pi);
            if (after && (v > bv || (v == bv && f < bi))) { bv = v; bi = f; }
        }
        s_bv[tid] = bv; s_bi[tid] = bi;
        __syncthreads();
        for (int s = 128; s > 0; s >>= 1) {
            if (tid < s) {
                if (s_bv[tid + s] > s_bv[tid] ||
                    (s_bv[tid + s] == s_bv[tid] && s_bi[tid + s] >= 0 &&
                     (s_bi[tid] < 0 || s_bi[tid + s] < s_bi[tid]))) {
                    s_bv[tid] = s_bv[tid + s]; s_bi[tid] = s_bi[tid + s];
                }
            }
            __syncthreads();
        }
        pv = s_bv[0]; pi = s_bi[0];
        __syncthreads();
        if (tid == 0) {
            const float v = fmaxf((float)pv, 0.f);
            g_tk_idx[row * TOPK + t] = pi;
            g_tk_val[row * TOPK + t] = v;
            H[(size_t)row * DSAE + pi] = v;
            if (v > 0.f) s_l0++;
        }
        __syncthreads();
    }
    if (tid == 0) atomicAdd(&g_l0_sum, (float)s_l0);
}

// ---------------- decoder: x_hat = h_sparse @ W_dec + b_dec, + loss ----------------
__global__ __launch_bounds__(256)
void decoder_kernel(const float* __restrict__ x, const float* __restrict__ Wdec,
                    const float* __restrict__ bdec, float* __restrict__ xhat)
{
    __shared__ int   sidx[TOPK];
    __shared__ float sval[TOPK];
    __shared__ float red[256];

    const int row = blockIdx.x;
    const int tid = threadIdx.x;
    if (tid < TOPK) {
        sidx[tid] = g_tk_idx[row * TOPK + tid];
        sval[tid] = g_tk_val[row * TOPK + tid];
    }
    __syncthreads();

    const int c = tid * 4;
    float4 acc = *reinterpret_cast<const float4*>(&bdec[c]);
    #pragma unroll 4
    for (int j = 0; j < TOPK; j++) {
        const float v = sval[j];
        const float4 w = *reinterpret_cast<const float4*>(&Wdec[(size_t)sidx[j] * DIN + c]);
        acc.x += v * w.x;
        acc.y += v * w.y;
        acc.z += v * w.z;
        acc.w += v * w.w;
    }
    const float4 xv = *reinterpret_cast<const float4*>(&x[(size_t)row * DIN + c]);
    *reinterpret_cast<float4*>(&xhat[(size_t)row * DIN + c]) = acc;

    const float dx = acc.x - xv.x, dy = acc.y - xv.y;
    const float dz = acc.z - xv.z, dw = acc.w - xv.w;
    red[tid] = dx * dx + dy * dy + dz * dz + dw * dw;
    __syncthreads();
    for (int s = 128; s > 0; s >>= 1) {
        if (tid < s) red[tid] += red[tid + s];
        __syncthreads();
    }
    if (tid == 0) atomicAdd(&g_loss_sum, (double)red[0]);
}

__global__ void finalize_kernel(float* __restrict__ out_loss, float* __restrict__ out_l0)
{
    out_loss[0] = (float)(g_loss_sum / ((double)BATCH * (double)DIN));
    out_l0[0]   = g_l0_sum / (float)BATCH;
}

// ---------------- launch ----------------
extern "C" void kernel_launch(void* const* d_in, const int* in_sizes, int n_in,
                              void* d_out, int out_size)
{
    const float* x     = (const float*)d_in[0];
    const float* W_enc = (const float*)d_in[1];
    const float* b_enc = (const float*)d_in[2];
    const float* W_dec = (const float*)d_in[3];
    const float* b_dec = (const float*)d_in[4];

    float* out   = (float*)d_out;
    float* xhat  = out;
    float* H     = out + (size_t)BATCH * DIN;
    float* oloss = out + (size_t)BATCH * DIN + (size_t)BATCH * DSAE;
    float* ol0   = oloss + 1;

    (void)in_sizes; (void)n_in; (void)out_size;

    cudaFuncSetAttribute(gemm_mma_kernel,
                         cudaFuncAttributeMaxDynamicSharedMemorySize, SM_TOTAL);

    init_kernel<<<BATCH / 256, 256>>>();

    splitx_kernel<<<BATCH / 8, 256>>>(x);
    dim3 wb(32, 8);
    splitw_kernel<<<dim3(DSAE / 32, DIN / 32), wb>>>(W_enc);

    dim3 gg(DSAE / 128, BATCH / 128);  // (128, 64)
    gemm_mma_kernel<<<gg, 256, SM_TOTAL>>>(b_enc, H);

    select_kernel<<<BATCH, 128>>>(x, b_enc, H);

    fallback_kernel<<<BATCH, 256>>>(x, b_enc, H);

    decoder_kernel<<<BATCH, 256>>>(x, W_dec, b_dec, xhat);

    finalize_kernel<<<1, 1>>>(oloss, ol0);
}